// round 3
// baseline (speedup 1.0000x reference)
#include <cuda_runtime.h>
#include <math.h>

#define BB 4
#define TT 256
#define SSL 512
#define DDIM 512
#define VV 50257

constexpr int ROWS = BB * TT;                       // 1024
constexpr long long LOGN = (long long)ROWS * VV;    // 51,463,168 (even, %4==0)

// ---------------- device scratch (no allocations allowed) ----------------
__device__ float g_proj[BB * SSL * DDIM];      // [B,S,D] projected memory
__device__ float g_attn[BB * TT * SSL];        // scores -> attn probs (in place)
__device__ float g_attnout[BB * TT * DDIM];    // [B,T,D]
__device__ float g_cat[BB * TT * 2 * DDIM];    // [B,T,2D]
__device__ float g_decattn[BB * TT * DDIM];    // [B,T,D]
__device__ float g_pgen[ROWS];
__device__ float g_rmax[ROWS];
__device__ float g_rsum[ROWS];
__device__ float g_logits[LOGN];               // [B,T,V] ~206MB
__device__ int   g_is64;                       // 1 if ids/slen are int64

// ---------------- dtype detection ----------------
// slen values are in [1, S]. If the buffer is int64 (little-endian), its int32
// view is [v0, 0, v1, 0, ...] -> zero high-words are invalid lengths -> int64.
__global__ void detect_k(const int* __restrict__ slen32)
{
    int ok32 = 1;
    for (int b = 0; b < BB; b++) {
        int v = slen32[b];
        if (v < 1 || v > SSL) ok32 = 0;
    }
    g_is64 = ok32 ? 0 : 1;
}

__device__ __forceinline__ int load_idx(const void* p, int i)
{
    return g_is64 ? (int)((const long long*)p)[i] : ((const int*)p)[i];
}

// ---------------- generic tiled SGEMM ----------------
// C[m,n] = act( sum_k A[m,k] * B'[k,n] + bias[n] )
// TB=false: B is [K,N] row-major. TB=true: B is [N,K] row-major (C = A @ B^T).
template <int BM, int BN, int BK, int TM, int TN, bool TB>
__global__ void gemm_k(const float* __restrict__ A, const float* __restrict__ B,
                       const float* __restrict__ bias, float* __restrict__ C,
                       int M, int N, int K,
                       long long sA, long long sB, long long sC, int act)
{
    constexpr int THREADS = (BM / TM) * (BN / TN);
    __shared__ float As[BK][BM];
    __shared__ float Bs[BK][BN];

    A += (long long)blockIdx.z * sA;
    B += (long long)blockIdx.z * sB;
    C += (long long)blockIdx.z * sC;

    const int m0 = blockIdx.x * BM;
    const int n0 = blockIdx.y * BN;
    const int tid = threadIdx.x;
    const int tx = tid % (BN / TN);
    const int ty = tid / (BN / TN);

    float acc[TM][TN];
#pragma unroll
    for (int i = 0; i < TM; i++)
#pragma unroll
        for (int j = 0; j < TN; j++) acc[i][j] = 0.f;

    for (int k0 = 0; k0 < K; k0 += BK) {
        // A tile: float4 along K (K % 4 == 0, rows 16B-aligned at all call sites)
        for (int idx = tid; idx < BM * (BK / 4); idx += THREADS) {
            int r = idx / (BK / 4);
            int c = (idx % (BK / 4)) * 4;
            float4 v = make_float4(0.f, 0.f, 0.f, 0.f);
            int gr = m0 + r;
            if (gr < M)
                v = *reinterpret_cast<const float4*>(&A[(long long)gr * K + k0 + c]);
            As[c + 0][r] = v.x; As[c + 1][r] = v.y;
            As[c + 2][r] = v.z; As[c + 3][r] = v.w;
        }
        if (TB) {
            for (int idx = tid; idx < BN * (BK / 4); idx += THREADS) {
                int r = idx / (BK / 4);
                int c = (idx % (BK / 4)) * 4;
                float4 v = make_float4(0.f, 0.f, 0.f, 0.f);
                int gn = n0 + r;
                if (gn < N)
                    v = *reinterpret_cast<const float4*>(&B[(long long)gn * K + k0 + c]);
                Bs[c + 0][r] = v.x; Bs[c + 1][r] = v.y;
                Bs[c + 2][r] = v.z; Bs[c + 3][r] = v.w;
            }
        } else {
            // scalar loads: N may be odd (V=50257), B rows not 16B aligned
            for (int idx = tid; idx < BK * BN; idx += THREADS) {
                int kk = idx / BN;
                int nn = idx % BN;
                int gn = n0 + nn;
                float v = 0.f;
                if (gn < N) v = B[(long long)(k0 + kk) * N + gn];
                Bs[kk][nn] = v;
            }
        }
        __syncthreads();

#pragma unroll
        for (int kk = 0; kk < BK; kk++) {
            float ra[TM], rb[TN];
#pragma unroll
            for (int i = 0; i < TM; i += 4) {
                float4 v = *reinterpret_cast<const float4*>(&As[kk][ty * TM + i]);
                ra[i] = v.x; ra[i + 1] = v.y; ra[i + 2] = v.z; ra[i + 3] = v.w;
            }
#pragma unroll
            for (int j = 0; j < TN; j += 4) {
                float4 v = *reinterpret_cast<const float4*>(&Bs[kk][tx * TN + j]);
                rb[j] = v.x; rb[j + 1] = v.y; rb[j + 2] = v.z; rb[j + 3] = v.w;
            }
#pragma unroll
            for (int i = 0; i < TM; i++)
#pragma unroll
                for (int j = 0; j < TN; j++)
                    acc[i][j] = fmaf(ra[i], rb[j], acc[i][j]);
        }
        __syncthreads();
    }

#pragma unroll
    for (int i = 0; i < TM; i++) {
        int gr = m0 + ty * TM + i;
        if (gr >= M) continue;
#pragma unroll
        for (int j = 0; j < TN; j++) {
            int gn = n0 + tx * TN + j;
            if (gn >= N) continue;
            float v = acc[i][j];
            if (bias) v += bias[gn];
            if (act == 1) v = tanhf(v);
            C[(long long)gr * N + gn] = v;
        }
    }
}

// ---------------- softmax over S with length mask (in place) ----------------
__global__ void softmax_s_k(float* __restrict__ attn, const void* __restrict__ slen)
{
    int row = blockIdx.x;              // b*T + t
    int b = row / TT;
    int L = load_idx(slen, b);
    float* p = attn + (long long)row * SSL;
    int tid = threadIdx.x;             // 256 threads, 2 elems each

    float v0 = p[tid];
    float v1 = p[tid + 256];
    bool a0 = tid < L;
    bool a1 = (tid + 256) < L;

    __shared__ float red[256];
    float m = fmaxf(a0 ? v0 : -INFINITY, a1 ? v1 : -INFINITY);
    red[tid] = m; __syncthreads();
    for (int off = 128; off > 0; off >>= 1) {
        if (tid < off) red[tid] = fmaxf(red[tid], red[tid + off]);
        __syncthreads();
    }
    float mx = red[0];
    __syncthreads();

    float e0 = a0 ? expf(v0 - mx) : 0.f;
    float e1 = a1 ? expf(v1 - mx) : 0.f;
    red[tid] = e0 + e1; __syncthreads();
    for (int off = 128; off > 0; off >>= 1) {
        if (tid < off) red[tid] += red[tid + off];
        __syncthreads();
    }
    float inv = 1.f / red[0];
    p[tid] = e0 * inv;
    p[tid + 256] = e1 * inv;
}

// ---------------- concat [dec | attn_out] ----------------
__global__ void concat_k(const float* __restrict__ dec, const float* __restrict__ ao,
                         float* __restrict__ cat)
{
    int i = blockIdx.x * blockDim.x + threadIdx.x;   // B*T*2D = 1M
    int row = i >> 10;          // / 1024
    int j = i & 1023;
    cat[i] = (j < DDIM) ? dec[row * DDIM + j] : ao[row * DDIM + (j - DDIM)];
}

// ---------------- p_gen = sigmoid(dec_attn . Wg + bg) ----------------
__global__ void pgen_k(const float* __restrict__ da, const float* __restrict__ Wg,
                       const float* __restrict__ bg, float* __restrict__ pg)
{
    int row = blockIdx.x;
    const float* p = da + (long long)row * DDIM;
    int tid = threadIdx.x;   // 128
    float acc = 0.f;
    for (int i = tid; i < DDIM; i += 128) acc += p[i] * Wg[i];
    __shared__ float red[128];
    red[tid] = acc; __syncthreads();
    for (int off = 64; off > 0; off >>= 1) {
        if (tid < off) red[tid] += red[tid + off];
        __syncthreads();
    }
    if (tid == 0) pg[row] = 1.f / (1.f + expf(-(red[0] + bg[0])));
}

// ---------------- per-row online max & sum(exp) over V ----------------
__global__ void stats_k(const float* __restrict__ logits,
                        float* __restrict__ rmax, float* __restrict__ rsum)
{
    int row = blockIdx.x;
    const float* p = logits + (long long)row * VV;
    int tid = threadIdx.x;   // 256
    float m = -INFINITY, s = 0.f;
    // vectorized main body: 50256 = 4*12564, one scalar tail element
    const float4* p4 = reinterpret_cast<const float4*>(p);  // row base 16B-aligned? row*VV odd stride
    // rows are NOT 16B aligned (VV odd) -> keep scalar loop (coalesced anyway)
    for (int i = tid; i < VV; i += 256) {
        float x = p[i];
        if (x > m) { s *= expf(m - x); m = x; }
        s += expf(x - m);
    }
    (void)p4;
    __shared__ float sm[256], ss[256];
    sm[tid] = m; ss[tid] = s; __syncthreads();
    for (int off = 128; off > 0; off >>= 1) {
        if (tid < off) {
            float m2 = sm[tid + off], s2 = ss[tid + off];
            float mm = fmaxf(sm[tid], m2);
            ss[tid] = ss[tid] * expf(sm[tid] - mm) + s2 * expf(m2 - mm);
            sm[tid] = mm;
        }
        __syncthreads();
    }
    if (tid == 0) { rmax[row] = sm[0]; rsum[row] = ss[0]; }
}

// ---------------- out = softmax(logits) * p_gen (flat, float4) ----------------
__global__ void genprob_k(const float* __restrict__ logits, const float* __restrict__ rmax,
                          const float* __restrict__ rsum, const float* __restrict__ pg,
                          float* __restrict__ out)
{
    long long i4 = (long long)(blockIdx.x) * blockDim.x + threadIdx.x;  // index into float4 space
    long long i = i4 * 4;
    if (i >= LOGN) return;
    float4 l = *reinterpret_cast<const float4*>(&logits[i]);   // LOGN%4==0, flat base aligned
    float4 o;
    int r0 = (int)(i / VV);
    int r3 = (int)((i + 3) / VV);
    if (r0 == r3) {
        float scale = pg[r0] / rsum[r0];
        float mx = rmax[r0];
        o.x = expf(l.x - mx) * scale;
        o.y = expf(l.y - mx) * scale;
        o.z = expf(l.z - mx) * scale;
        o.w = expf(l.w - mx) * scale;
    } else {  // straddles a row boundary (rare)
        float lv[4] = {l.x, l.y, l.z, l.w};
        float ov[4];
#pragma unroll
        for (int j = 0; j < 4; j++) {
            int r = (int)((i + j) / VV);
            ov[j] = expf(lv[j] - rmax[r]) * (pg[r] / rsum[r]);
        }
        o = make_float4(ov[0], ov[1], ov[2], ov[3]);
    }
    *reinterpret_cast<float4*>(&out[i]) = o;
}

// ---------------- scatter-add copy probs into vocab ----------------
__global__ void scatter_k(const float* __restrict__ attn, const float* __restrict__ pg,
                          const void* __restrict__ ids, float* __restrict__ out)
{
    int i = blockIdx.x * blockDim.x + threadIdx.x;   // B*T*S
    if (i >= BB * TT * SSL) return;
    int s = i % SSL;
    int row = i / SSL;
    int b = row / TT;
    float p = attn[i] * (1.f - pg[row]);
    if (p != 0.f) {
        int vid = load_idx(ids, b * SSL + s);
        atomicAdd(&out[(long long)row * VV + vid], p);
    }
}

// ---------------- final log (flat, float4) ----------------
__global__ void log_k(float* __restrict__ out)
{
    long long i4 = (long long)(blockIdx.x) * blockDim.x + threadIdx.x;
    long long i = i4 * 4;
    if (i >= LOGN) return;
    float4 v = *reinterpret_cast<float4*>(&out[i]);
    v.x = logf(v.x); v.y = logf(v.y); v.z = logf(v.z); v.w = logf(v.w);
    *reinterpret_cast<float4*>(&out[i]) = v;
}

// ---------------- host launcher ----------------
extern "C" void kernel_launch(void* const* d_in, const int* in_sizes, int n_in,
                              void* d_out, int out_size)
{
    const float* dec  = (const float*)d_in[0];   // [B,T,D]
    const float* mem  = (const float*)d_in[1];   // [B,S,D]
    const float* Wc   = (const float*)d_in[2];   // [D,D]
    const float* bc   = (const float*)d_in[3];   // [D]
    const float* Wd   = (const float*)d_in[4];   // [2D,D]
    const float* bd   = (const float*)d_in[5];   // [D]
    const float* Wg   = (const float*)d_in[6];   // [D,1]
    const float* bg   = (const float*)d_in[7];   // [1]
    const float* Wo   = (const float*)d_in[8];   // [D,V]
    const float* bo   = (const float*)d_in[9];   // [V]
    const void*  ids  = d_in[10];                // [B,S]  int32 or int64
    const void*  slen = d_in[11];                // [B]    int32 or int64
    float* out = (float*)d_out;

    float *proj, *attn, *attnout, *cat, *decat, *pg, *rmax, *rsum, *logits;
    cudaGetSymbolAddress((void**)&proj,    g_proj);
    cudaGetSymbolAddress((void**)&attn,    g_attn);
    cudaGetSymbolAddress((void**)&attnout, g_attnout);
    cudaGetSymbolAddress((void**)&cat,     g_cat);
    cudaGetSymbolAddress((void**)&decat,   g_decattn);
    cudaGetSymbolAddress((void**)&pg,      g_pgen);
    cudaGetSymbolAddress((void**)&rmax,    g_rmax);
    cudaGetSymbolAddress((void**)&rsum,    g_rsum);
    cudaGetSymbolAddress((void**)&logits,  g_logits);

    // 0) detect int32 vs int64 index buffers
    detect_k<<<1, 1>>>((const int*)slen);

    // 1) proj_mem = mem @ Wc + bc        [2048,512] x [512,512]
    gemm_k<128,128,8,8,8,false><<<dim3(16,4,1), 256>>>(
        mem, Wc, bc, proj, BB*SSL, DDIM, DDIM, 0, 0, 0, 0);

    // 2) scores = dec @ proj^T (batched NT)   per b: [256,512] x [512,512]^T
    gemm_k<64,64,8,4,4,true><<<dim3(4,8,BB), 256>>>(
        dec, proj, nullptr, attn, TT, SSL, DDIM,
        (long long)TT*DDIM, (long long)SSL*DDIM, (long long)TT*SSL, 0);

    // 3) masked softmax over S (in place)
    softmax_s_k<<<ROWS, 256>>>(attn, slen);

    // 4) attn_out = attn @ mem (batched NN)   per b: [256,512] x [512,512]
    gemm_k<64,64,8,4,4,false><<<dim3(4,8,BB), 256>>>(
        attn, mem, nullptr, attnout, TT, DDIM, SSL,
        (long long)TT*SSL, (long long)SSL*DDIM, (long long)TT*DDIM, 0);

    // 5) cat = [dec | attn_out]
    concat_k<<<(BB*TT*2*DDIM)/256, 256>>>(dec, attnout, cat);

    // 6) dec_attn = tanh(cat @ Wd + bd)   [1024,1024] x [1024,512]
    gemm_k<128,128,8,8,8,false><<<dim3(8,4,1), 256>>>(
        cat, Wd, bd, decat, ROWS, DDIM, 2*DDIM, 0, 0, 0, 1);

    // 7) p_gen
    pgen_k<<<ROWS, 128>>>(decat, Wg, bg, pg);

    // 8) logits = dec @ Wo + bo   [1024,512] x [512,50257]  (dominant GEMM)
    //    blockIdx.x = row tile so the 8 row-blocks of one Wo column stripe co-run.
    gemm_k<128,128,8,8,8,false><<<dim3(8,(VV+127)/128,1), 256>>>(
        dec, Wo, bo, logits, ROWS, VV, DDIM, 0, 0, 0, 0);

    // 9) per-row max/sumexp over V
    stats_k<<<ROWS, 256>>>(logits, rmax, rsum);

    // 10) out = softmax(logits) * p_gen     (flat float4 pass)
    long long n4 = LOGN / 4;
    genprob_k<<<(int)((n4 + 255) / 256), 256>>>(logits, rmax, rsum, pg, out);

    // 11) scatter-add copy probs
    scatter_k<<<(BB*TT*SSL)/256, 256>>>(attn, pg, ids, out);

    // 12) log                                (flat float4 pass)
    log_k<<<(int)((n4 + 255) / 256), 256>>>(out);
}

// round 4
// speedup vs baseline: 2.0955x; 2.0955x over previous
#include <cuda_runtime.h>
#include <math.h>
#include <stdint.h>

#define BB 4
#define TT 256
#define SSL 512
#define DDIM 512
#define VV 50257

constexpr int ROWS = BB * TT;                       // 1024
constexpr long long LOGN = (long long)ROWS * VV;    // 51,463,168 (%4 == 0)

// ---------------- device scratch ----------------
__device__ float g_proj[BB * SSL * DDIM];
__device__ float g_attn[BB * TT * SSL];
__device__ float g_attnout[BB * TT * DDIM];
__device__ float g_cat[BB * TT * 2 * DDIM];
__device__ float g_decattn[BB * TT * DDIM];
__device__ float g_pgen[ROWS];
__device__ float g_rmax[ROWS];
__device__ float g_rsum[ROWS];
__device__ float g_logits[LOGN];               // ~206MB
__device__ int   g_is64;
__device__ int   g_smap[BB * SSL];             // s -> unique slot
__device__ int   g_uniq[BB * SSL];             // unique vocab ids per batch
__device__ int   g_ucnt[BB];

// ---------------- dtype detection (int32 vs int64 index buffers) ----------------
__global__ void detect_k(const int* __restrict__ slen32)
{
    int ok32 = 1;
    for (int b = 0; b < BB; b++) {
        int v = slen32[b];
        if (v < 1 || v > SSL) ok32 = 0;
    }
    g_is64 = ok32 ? 0 : 1;
}

__device__ __forceinline__ int load_idx(const void* p, int i)
{
    return g_is64 ? (int)((const long long*)p)[i] : ((const int*)p)[i];
}

// ================= TF32 tensor-core GEMM =================
// C[M,N] = act(A[M,K] @ B[K,N] + bias). Row-major A,B.
// Block 128x128x32, 8 warps (2x4), warp tile 64x32 via mma.m16n8k8.
// Requires: M%128==0, K%32==0 (true at call sites). N guarded.
__device__ __forceinline__ uint32_t f2tf32(float f)
{
    uint32_t u;
    asm("cvt.rna.tf32.f32 %0, %1;" : "=r"(u) : "f"(f));
    return u;
}

template <bool TANH>
__global__ __launch_bounds__(256) void gemm_tf32_k(
    const float* __restrict__ A, const float* __restrict__ B,
    const float* __restrict__ bias, float* __restrict__ C,
    int M, int N, int K)
{
    __shared__ float As[32][136];   // As[k][m]  (stride 136: banks = 8t+g, conflict-free)
    __shared__ float Bs[32][136];   // Bs[k][n]

    const int tid = threadIdx.x;
    const int wid = tid >> 5, lane = tid & 31;
    const int wm = (wid >> 2) * 64, wn = (wid & 3) * 32;
    const int m0 = blockIdx.x * 128, n0 = blockIdx.y * 128;
    const int g = lane >> 2, t = lane & 3;

    float acc[4][4][4];
#pragma unroll
    for (int i = 0; i < 4; i++)
#pragma unroll
        for (int j = 0; j < 4; j++)
#pragma unroll
            for (int r = 0; r < 4; r++) acc[i][j][r] = 0.f;

    for (int k0 = 0; k0 < K; k0 += 32) {
        // A tile 128x32: float4 along K (rows always valid)
        for (int i = tid; i < 128 * 8; i += 256) {
            int r = i >> 3, c4 = (i & 7) * 4;
            float4 v = *reinterpret_cast<const float4*>(&A[(long long)(m0 + r) * K + k0 + c4]);
            As[c4 + 0][r] = v.x; As[c4 + 1][r] = v.y;
            As[c4 + 2][r] = v.z; As[c4 + 3][r] = v.w;
        }
        // B tile 32x128: coalesced scalar (N odd), guard col
        for (int i = tid; i < 32 * 128; i += 256) {
            int kk = i >> 7, nn = i & 127;
            int gn = n0 + nn;
            Bs[kk][nn] = (gn < N) ? B[(long long)(k0 + kk) * N + gn] : 0.f;
        }
        __syncthreads();

#pragma unroll
        for (int ks = 0; ks < 32; ks += 8) {
            uint32_t a[4][4], b[4][2];
#pragma unroll
            for (int mf = 0; mf < 4; mf++) {
                int r = wm + mf * 16;
                a[mf][0] = f2tf32(As[ks + t    ][r + g]);
                a[mf][1] = f2tf32(As[ks + t    ][r + g + 8]);
                a[mf][2] = f2tf32(As[ks + t + 4][r + g]);
                a[mf][3] = f2tf32(As[ks + t + 4][r + g + 8]);
            }
#pragma unroll
            for (int nf = 0; nf < 4; nf++) {
                int c = wn + nf * 8;
                b[nf][0] = f2tf32(Bs[ks + t    ][c + g]);
                b[nf][1] = f2tf32(Bs[ks + t + 4][c + g]);
            }
#pragma unroll
            for (int mf = 0; mf < 4; mf++)
#pragma unroll
                for (int nf = 0; nf < 4; nf++) {
                    float* d = acc[mf][nf];
                    asm volatile(
                        "mma.sync.aligned.m16n8k8.row.col.f32.tf32.tf32.f32 "
                        "{%0,%1,%2,%3}, {%4,%5,%6,%7}, {%8,%9}, {%0,%1,%2,%3};"
                        : "+f"(d[0]), "+f"(d[1]), "+f"(d[2]), "+f"(d[3])
                        : "r"(a[mf][0]), "r"(a[mf][1]), "r"(a[mf][2]), "r"(a[mf][3]),
                          "r"(b[nf][0]), "r"(b[nf][1]));
                }
        }
        __syncthreads();
    }

    // epilogue: c0=(g,2t) c1=(g,2t+1) c2=(g+8,2t) c3=(g+8,2t+1)
#pragma unroll
    for (int mf = 0; mf < 4; mf++) {
        int r0 = m0 + wm + mf * 16 + g;
        int r1 = r0 + 8;
#pragma unroll
        for (int nf = 0; nf < 4; nf++) {
            int c0 = n0 + wn + nf * 8 + 2 * t;
#pragma unroll
            for (int e = 0; e < 4; e++) {
                int gr = (e < 2) ? r0 : r1;
                int gc = c0 + (e & 1);
                if (gc < N) {
                    float v = acc[mf][nf][e] + (bias ? bias[gc] : 0.f);
                    if (TANH) v = tanhf(v);
                    C[(long long)gr * N + gc] = v;
                }
            }
        }
    }
}

// ---------------- generic tiled SGEMM (fp32 exact — attention-score path) ----------------
template <int BM, int BN, int BK, int TM, int TN, bool TB>
__global__ void gemm_k(const float* __restrict__ A, const float* __restrict__ B,
                       const float* __restrict__ bias, float* __restrict__ C,
                       int M, int N, int K,
                       long long sA, long long sB, long long sC, int act)
{
    constexpr int THREADS = (BM / TM) * (BN / TN);
    __shared__ float As[BK][BM];
    __shared__ float Bs[BK][BN];

    A += (long long)blockIdx.z * sA;
    B += (long long)blockIdx.z * sB;
    C += (long long)blockIdx.z * sC;

    const int m0 = blockIdx.x * BM;
    const int n0 = blockIdx.y * BN;
    const int tid = threadIdx.x;
    const int tx = tid % (BN / TN);
    const int ty = tid / (BN / TN);

    float acc[TM][TN];
#pragma unroll
    for (int i = 0; i < TM; i++)
#pragma unroll
        for (int j = 0; j < TN; j++) acc[i][j] = 0.f;

    for (int k0 = 0; k0 < K; k0 += BK) {
        for (int idx = tid; idx < BM * (BK / 4); idx += THREADS) {
            int r = idx / (BK / 4);
            int c = (idx % (BK / 4)) * 4;
            float4 v = make_float4(0.f, 0.f, 0.f, 0.f);
            int gr = m0 + r;
            if (gr < M)
                v = *reinterpret_cast<const float4*>(&A[(long long)gr * K + k0 + c]);
            As[c + 0][r] = v.x; As[c + 1][r] = v.y;
            As[c + 2][r] = v.z; As[c + 3][r] = v.w;
        }
        if (TB) {
            for (int idx = tid; idx < BN * (BK / 4); idx += THREADS) {
                int r = idx / (BK / 4);
                int c = (idx % (BK / 4)) * 4;
                float4 v = make_float4(0.f, 0.f, 0.f, 0.f);
                int gn = n0 + r;
                if (gn < N)
                    v = *reinterpret_cast<const float4*>(&B[(long long)gn * K + k0 + c]);
                Bs[c + 0][r] = v.x; Bs[c + 1][r] = v.y;
                Bs[c + 2][r] = v.z; Bs[c + 3][r] = v.w;
            }
        } else {
            for (int idx = tid; idx < BK * BN; idx += THREADS) {
                int kk = idx / BN;
                int nn = idx % BN;
                int gn = n0 + nn;
                float v = 0.f;
                if (gn < N) v = B[(long long)(k0 + kk) * N + gn];
                Bs[kk][nn] = v;
            }
        }
        __syncthreads();

#pragma unroll
        for (int kk = 0; kk < BK; kk++) {
            float ra[TM], rb[TN];
#pragma unroll
            for (int i = 0; i < TM; i += 4) {
                float4 v = *reinterpret_cast<const float4*>(&As[kk][ty * TM + i]);
                ra[i] = v.x; ra[i + 1] = v.y; ra[i + 2] = v.z; ra[i + 3] = v.w;
            }
#pragma unroll
            for (int j = 0; j < TN; j += 4) {
                float4 v = *reinterpret_cast<const float4*>(&Bs[kk][tx * TN + j]);
                rb[j] = v.x; rb[j + 1] = v.y; rb[j + 2] = v.z; rb[j + 3] = v.w;
            }
#pragma unroll
            for (int i = 0; i < TM; i++)
#pragma unroll
                for (int j = 0; j < TN; j++)
                    acc[i][j] = fmaf(ra[i], rb[j], acc[i][j]);
        }
        __syncthreads();
    }

#pragma unroll
    for (int i = 0; i < TM; i++) {
        int gr = m0 + ty * TM + i;
        if (gr >= M) continue;
#pragma unroll
        for (int j = 0; j < TN; j++) {
            int gn = n0 + tx * TN + j;
            if (gn >= N) continue;
            float v = acc[i][j];
            if (bias) v += bias[gn];
            if (act == 1) v = tanhf(v);
            C[(long long)gr * N + gn] = v;
        }
    }
}

// ---------------- softmax over S with length mask ----------------
__global__ void softmax_s_k(float* __restrict__ attn, const void* __restrict__ slen)
{
    int row = blockIdx.x;
    int b = row / TT;
    int L = load_idx(slen, b);
    float* p = attn + (long long)row * SSL;
    int tid = threadIdx.x;   // 256

    float v0 = p[tid];
    float v1 = p[tid + 256];
    bool a0 = tid < L;
    bool a1 = (tid + 256) < L;

    __shared__ float red[256];
    float m = fmaxf(a0 ? v0 : -INFINITY, a1 ? v1 : -INFINITY);
    red[tid] = m; __syncthreads();
    for (int off = 128; off > 0; off >>= 1) {
        if (tid < off) red[tid] = fmaxf(red[tid], red[tid + off]);
        __syncthreads();
    }
    float mx = red[0];
    __syncthreads();

    float e0 = a0 ? expf(v0 - mx) : 0.f;
    float e1 = a1 ? expf(v1 - mx) : 0.f;
    red[tid] = e0 + e1; __syncthreads();
    for (int off = 128; off > 0; off >>= 1) {
        if (tid < off) red[tid] += red[tid + off];
        __syncthreads();
    }
    float inv = 1.f / red[0];
    p[tid] = e0 * inv;
    p[tid + 256] = e1 * inv;
}

// ---------------- concat [dec | attn_out] ----------------
__global__ void concat_k(const float* __restrict__ dec, const float* __restrict__ ao,
                         float* __restrict__ cat)
{
    int i = blockIdx.x * blockDim.x + threadIdx.x;
    int row = i >> 10;
    int j = i & 1023;
    cat[i] = (j < DDIM) ? dec[row * DDIM + j] : ao[row * DDIM + (j - DDIM)];
}

// ---------------- p_gen ----------------
__global__ void pgen_k(const float* __restrict__ da, const float* __restrict__ Wg,
                       const float* __restrict__ bg, float* __restrict__ pg)
{
    int row = blockIdx.x;
    const float* p = da + (long long)row * DDIM;
    int tid = threadIdx.x;   // 128
    float acc = 0.f;
    for (int i = tid; i < DDIM; i += 128) acc += p[i] * Wg[i];
    __shared__ float red[128];
    red[tid] = acc; __syncthreads();
    for (int off = 64; off > 0; off >>= 1) {
        if (tid < off) red[tid] += red[tid + off];
        __syncthreads();
    }
    if (tid == 0) pg[row] = 1.f / (1.f + expf(-(red[0] + bg[0])));
}

// ---------------- per-row max & sum(exp) over V ----------------
__global__ void stats_k(const float* __restrict__ logits,
                        float* __restrict__ rmax, float* __restrict__ rsum)
{
    int row = blockIdx.x;
    const float* p = logits + (long long)row * VV;
    int tid = threadIdx.x;   // 256
    float m = -INFINITY, s = 0.f;
    for (int i = tid; i < VV; i += 256) {
        float x = p[i];
        if (x > m) { s *= __expf(m - x); m = x; }
        s += __expf(x - m);
    }
    __shared__ float sm[256], ss[256];
    sm[tid] = m; ss[tid] = s; __syncthreads();
    for (int off = 128; off > 0; off >>= 1) {
        if (tid < off) {
            float m2 = sm[tid + off], s2 = ss[tid + off];
            float mm = fmaxf(sm[tid], m2);
            ss[tid] = ss[tid] * __expf(sm[tid] - mm) + s2 * __expf(m2 - mm);
            sm[tid] = mm;
        }
        __syncthreads();
    }
    if (tid == 0) { rmax[row] = sm[0]; rsum[row] = ss[0]; }
}

// ---------------- main pass: out = logit - rmax + log(pg/rsum)  (exact identity) ----------------
__global__ void mainpass_k(const float* __restrict__ logits, const float* __restrict__ rmax,
                           const float* __restrict__ rsum, const float* __restrict__ pg,
                           float* __restrict__ out)
{
    long long i = ((long long)blockIdx.x * blockDim.x + threadIdx.x) * 4;
    if (i >= LOGN) return;
    float4 l = *reinterpret_cast<const float4*>(&logits[i]);
    float4 o;
    int r0 = (int)(i / VV);
    int r3 = (int)((i + 3) / VV);
    if (r0 == r3) {
        float c = logf(pg[r0] / rsum[r0]) - rmax[r0];
        o.x = l.x + c; o.y = l.y + c; o.z = l.z + c; o.w = l.w + c;
    } else {
        float lv[4] = {l.x, l.y, l.z, l.w};
        float ov[4];
#pragma unroll
        for (int j = 0; j < 4; j++) {
            int r = (int)((i + j) / VV);
            ov[j] = lv[j] + logf(pg[r] / rsum[r]) - rmax[r];
        }
        o = make_float4(ov[0], ov[1], ov[2], ov[3]);
    }
    *reinterpret_cast<float4*>(&out[i]) = o;
}

// ---------------- per-batch unique-id hash table ----------------
__global__ void hash_k(const void* __restrict__ ids)
{
    int b = blockIdx.x;
    int tid = threadIdx.x;     // 512
    __shared__ int key[1024];
    __shared__ int val[1024];
    __shared__ int cnt;
    key[tid] = -1; key[tid + 512] = -1;
    val[tid] = -1; val[tid + 512] = -1;
    if (tid == 0) cnt = 0;
    __syncthreads();

    int id = load_idx(ids, b * SSL + tid);
    unsigned h = ((unsigned)id * 2654435761u) & 1023u;
    int myh = -1;
    for (;;) {
        int old = atomicCAS(&key[h], -1, id);
        if (old == -1) { myh = (int)h; break; }
        if (old == id) break;
        h = (h + 1) & 1023u;
    }
    __syncthreads();
    if (myh >= 0) {
        int u = atomicAdd(&cnt, 1);
        val[myh] = u;
        g_uniq[b * SSL + u] = id;
    }
    __syncthreads();
    h = ((unsigned)id * 2654435761u) & 1023u;
    while (key[h] != id) h = (h + 1) & 1023u;
    g_smap[b * SSL + tid] = val[h];
    if (tid == 0) g_ucnt[b] = cnt;
}

// ---------------- fixup: exact value at scatter-touched entries ----------------
__global__ void fixup_k(const float* __restrict__ attn, const float* __restrict__ logits,
                        const float* __restrict__ pg, const float* __restrict__ rmax,
                        const float* __restrict__ rsum, float* __restrict__ out)
{
    int row = blockIdx.x;
    int b = row / TT;
    int tid = threadIdx.x;   // 512
    __shared__ float acc[512];
    acc[tid] = 0.f;
    __syncthreads();
    float a = attn[(long long)row * SSL + tid];
    atomicAdd(&acc[g_smap[b * SSL + tid]], a);
    __syncthreads();
    int U = g_ucnt[b];
    float p = pg[row];
    float scale = p / rsum[row];
    float mx = rmax[row];
    float q = 1.f - p;
    if (tid < U) {
        int vid = g_uniq[b * SSL + tid];
        long long idx = (long long)row * VV + vid;
        float l = logits[idx];
        out[idx] = logf(expf(l - mx) * scale + acc[tid] * q);
    }
}

// ---------------- host launcher ----------------
extern "C" void kernel_launch(void* const* d_in, const int* in_sizes, int n_in,
                              void* d_out, int out_size)
{
    const float* dec  = (const float*)d_in[0];
    const float* mem  = (const float*)d_in[1];
    const float* Wc   = (const float*)d_in[2];
    const float* bc   = (const float*)d_in[3];
    const float* Wd   = (const float*)d_in[4];
    const float* bd   = (const float*)d_in[5];
    const float* Wg   = (const float*)d_in[6];
    const float* bg   = (const float*)d_in[7];
    const float* Wo   = (const float*)d_in[8];
    const float* bo   = (const float*)d_in[9];
    const void*  ids  = d_in[10];
    const void*  slen = d_in[11];
    float* out = (float*)d_out;

    float *proj, *attn, *attnout, *cat, *decat, *pg, *rmax, *rsum, *logits;
    cudaGetSymbolAddress((void**)&proj,    g_proj);
    cudaGetSymbolAddress((void**)&attn,    g_attn);
    cudaGetSymbolAddress((void**)&attnout, g_attnout);
    cudaGetSymbolAddress((void**)&cat,     g_cat);
    cudaGetSymbolAddress((void**)&decat,   g_decattn);
    cudaGetSymbolAddress((void**)&pg,      g_pgen);
    cudaGetSymbolAddress((void**)&rmax,    g_rmax);
    cudaGetSymbolAddress((void**)&rsum,    g_rsum);
    cudaGetSymbolAddress((void**)&logits,  g_logits);

    // 0) dtype detect + per-batch vocab hash
    detect_k<<<1, 1>>>((const int*)slen);
    hash_k<<<BB, 512>>>(ids);

    // 1) proj_mem = mem @ Wc + bc  (fp32 exact — feeds softmax exponents)
    gemm_k<128,128,8,8,8,false><<<dim3(16,4,1), 256>>>(
        mem, Wc, bc, proj, BB*SSL, DDIM, DDIM, 0, 0, 0, 0);

    // 2) scores = dec @ proj^T (batched NT, fp32 exact)
    gemm_k<64,64,8,4,4,true><<<dim3(4,8,BB), 256>>>(
        dec, proj, nullptr, attn, TT, SSL, DDIM,
        (long long)TT*DDIM, (long long)SSL*DDIM, (long long)TT*SSL, 0);

    // 3) masked softmax over S
    softmax_s_k<<<ROWS, 256>>>(attn, slen);

    // 4) attn_out = attn @ mem (batched NN, fp32)
    gemm_k<64,64,8,4,4,false><<<dim3(4,8,BB), 256>>>(
        attn, mem, nullptr, attnout, TT, DDIM, SSL,
        (long long)TT*SSL, (long long)SSL*DDIM, (long long)TT*DDIM, 0);

    // 5) cat = [dec | attn_out]
    concat_k<<<(BB*TT*2*DDIM)/256, 256>>>(dec, attnout, cat);

    // 6) dec_attn = tanh(cat @ Wd + bd)   — TF32 tensor cores
    gemm_tf32_k<true><<<dim3(8,4,1), 256>>>(cat, Wd, bd, decat, ROWS, DDIM, 2*DDIM);

    // 7) p_gen
    pgen_k<<<ROWS, 128>>>(decat, Wg, bg, pg);

    // 8) logits = dec @ Wo + bo   — TF32 tensor cores (dominant GEMM)
    gemm_tf32_k<false><<<dim3(8,(VV+127)/128,1), 256>>>(dec, Wo, bo, logits, ROWS, VV, DDIM);

    // 9) per-row max / sumexp over V
    stats_k<<<ROWS, 256>>>(logits, rmax, rsum);

    // 10) out = logit - rmax + log(pg/rsum)   (exact log-identity, no exp/log round trip)
    long long n4 = LOGN / 4;
    mainpass_k<<<(int)((n4 + 255) / 256), 256>>>(logits, rmax, rsum, pg, out);

    // 11) exact fixup at scatter-touched entries (no global atomics)
    fixup_k<<<ROWS, 512>>>(attn, logits, pg, rmax, rsum, out);
}